// round 10
// baseline (speedup 1.0000x reference)
#include <cuda_runtime.h>
#include <cuda_bf16.h>
#include <cuda_fp16.h>
#include <math.h>
#include <stdint.h>

#define BATCH 4096
#define HID 128
#define NSTEP 16

// ---------------- persistent state (device globals; no allocations) ----------
__device__ __align__(16) float d_h[BATCH * HID];
__device__ __align__(16) float d_c[BATCH * HID];
__device__ __align__(16) __nv_bfloat16 d_h_hi[BATCH * HID];
__device__ __align__(16) __nv_bfloat16 d_h_lo[BATCH * HID];
__device__ __align__(16) __nv_bfloat16 d_x_hi[BATCH * 64];
__device__ __align__(16) __nv_bfloat16 d_x_lo[BATCH * 64];
__device__ __align__(16) __nv_bfloat16 d_W_hi[512 * 192];   // reordered cols: n' = j*4+gate
__device__ __align__(16) __nv_bfloat16 d_W_lo[512 * 192];
__device__ __align__(16) float d_bias[512];                  // reordered
__device__ __align__(16) __half d_img_h[(size_t)BATCH * 2 * 4096];  // fp16 images (67MB)

// ---------------- helpers ----------------------------------------------------
__device__ __forceinline__ uint32_t smem_u32(const void* p) {
    uint32_t a;
    asm("{ .reg .u64 t; cvta.to.shared.u64 t, %1; cvt.u32.u64 %0, t; }" : "=r"(a) : "l"(p));
    return a;
}
__device__ __forceinline__ void cp_async16(uint32_t dst, const void* src) {
    asm volatile("cp.async.cg.shared.global [%0], [%1], 16;" :: "r"(dst), "l"(src) : "memory");
}
__device__ __forceinline__ void cp_commit() {
    asm volatile("cp.async.commit_group;" ::: "memory");
}
template <int N>
__device__ __forceinline__ void cp_wait() {
    asm volatile("cp.async.wait_group %0;" :: "n"(N) : "memory");
}
__device__ __forceinline__ void pdl_trigger() {
    asm volatile("griddepcontrol.launch_dependents;");
}
__device__ __forceinline__ void pdl_wait() {
    asm volatile("griddepcontrol.wait;" ::: "memory");
}
__device__ __forceinline__ void ldm_x4(uint32_t* r, uint32_t a) {
    asm volatile("ldmatrix.sync.aligned.m8n8.x4.shared.b16 {%0,%1,%2,%3}, [%4];"
                 : "=r"(r[0]), "=r"(r[1]), "=r"(r[2]), "=r"(r[3]) : "r"(a));
}
__device__ __forceinline__ void ldm_x4_t(uint32_t* r, uint32_t a) {
    asm volatile("ldmatrix.sync.aligned.m8n8.x4.trans.shared.b16 {%0,%1,%2,%3}, [%4];"
                 : "=r"(r[0]), "=r"(r[1]), "=r"(r[2]), "=r"(r[3]) : "r"(a));
}
__device__ __forceinline__ void ldm_x2(uint32_t* r, uint32_t a) {
    asm volatile("ldmatrix.sync.aligned.m8n8.x2.shared.b16 {%0,%1}, [%2];"
                 : "=r"(r[0]), "=r"(r[1]) : "r"(a));
}
__device__ __forceinline__ void mma_bf16(float* d, const uint32_t* a, const uint32_t* b) {
    asm volatile(
        "mma.sync.aligned.m16n8k16.row.col.f32.bf16.bf16.f32 "
        "{%0,%1,%2,%3}, {%4,%5,%6,%7}, {%8,%9}, {%0,%1,%2,%3};"
        : "+f"(d[0]), "+f"(d[1]), "+f"(d[2]), "+f"(d[3])
        : "r"(a[0]), "r"(a[1]), "r"(a[2]), "r"(a[3]), "r"(b[0]), "r"(b[1]));
}
__device__ __forceinline__ void mma_f16(float* d, const uint32_t* a, const uint32_t* b) {
    asm volatile(
        "mma.sync.aligned.m16n8k16.row.col.f32.f16.f16.f32 "
        "{%0,%1,%2,%3}, {%4,%5,%6,%7}, {%8,%9}, {%0,%1,%2,%3};"
        : "+f"(d[0]), "+f"(d[1]), "+f"(d[2]), "+f"(d[3])
        : "r"(a[0]), "r"(a[1]), "r"(a[2]), "r"(a[3]), "r"(b[0]), "r"(b[1]));
}
__device__ __forceinline__ uint32_t pack_h2(float x, float y) {
    __half2 h = __floats2half2_rn(x, y);
    return *reinterpret_cast<uint32_t*>(&h);
}

// ---------------- merged prologue --------------------------------------------
// blocks [0,8192): img fp32->fp16;  [8192,10240): zero state;  [10240,10624): weights
__global__ void prologue_kernel(const float* __restrict__ imgs,
                                const float* __restrict__ W_ih,
                                const float* __restrict__ W_hh,
                                const float* __restrict__ b_ih,
                                const float* __restrict__ b_hh) {
    int bid = blockIdx.x, tid = threadIdx.x;
    if (bid < 8192) {
        const float4* in4 = reinterpret_cast<const float4*>(imgs);
        uint2* out2 = reinterpret_cast<uint2*>(d_img_h);
        for (int i = bid * 256 + tid; i < 8388608; i += 8192 * 256) {
            float4 v = in4[i];
            __half2 a = __floats2half2_rn(v.x, v.y);
            __half2 c = __floats2half2_rn(v.z, v.w);
            uint2 o;
            o.x = *reinterpret_cast<uint32_t*>(&a);
            o.y = *reinterpret_cast<uint32_t*>(&c);
            out2[i] = o;
        }
    } else if (bid < 10240) {
        int i = (bid - 8192) * 256 + tid;    // exactly BATCH*HID
        d_h[i] = 0.0f; d_c[i] = 0.0f;
        d_h_hi[i] = __float2bfloat16(0.0f);
        d_h_lo[i] = __float2bfloat16(0.0f);
    } else {
        int idx = (bid - 10240) * 256 + tid; // exactly 512*192
        int np = idx / 192, k = idx % 192;
        int gate = np & 3, j = np >> 2;
        int orig = gate * 128 + j;
        float w = (k < 64) ? W_ih[orig * 64 + k] : W_hh[orig * 128 + (k - 64)];
        __nv_bfloat16 hi = __float2bfloat16(w);
        __nv_bfloat16 lo = __float2bfloat16(w - __bfloat162float(hi));
        d_W_hi[np * 192 + k] = hi;
        d_W_lo[np * 192 + k] = lo;
        if (k == 0) d_bias[np] = b_ih[orig] + b_hh[orig];
    }
}

// ---------------- glimpse (tensor-core, packed hi/lo, EXPLICIT norm) ---------
// 128 threads = 4 warps, one sample per warp.
// smem: img[s] @ s*9216 (64 rows x 144B fp16)
//       FhA[s] @ 36864 + s*2304 (16 rows x 144B: rows 0-7 = hi, 8-15 = lo)
//       FwB[s] @ 46080 + s*2304 (hi 8 rows @0, lo 8 rows @1152)
#define GL2_IMG(s)    ((s) * 9216)
#define GL2_FH(s)     (36864 + (s) * 2304)
#define GL2_FW(s)     (46080 + (s) * 2304)
#define GL2_TOTAL     55296

__global__ __launch_bounds__(128) void glimpse_kernel(
    int sel, const float* __restrict__ W_g, const float* __restrict__ b_g)
{
    extern __shared__ char gsm[];
    uint32_t sb = smem_u32(gsm);
    int tid = threadIdx.x, wid = tid >> 5, lane = tid & 31;
    int b0 = blockIdx.x * 4;
    int b = b0 + wid;

    // ---- static prefetch (images) BEFORE grid-dependency wait ----
#pragma unroll
    for (int j = 0; j < 16; j++) {
        int idx = tid + j * 128;
        int s = idx >> 9, r = (idx >> 3) & 63, c = idx & 7;
        const __half* src = d_img_h + ((size_t)(b0 + s) * 2 + (size_t)sel) * 4096 + r * 64 + c * 8;
        cp_async16(sb + GL2_IMG(s) + r * 144 + c * 16, src);
    }
    cp_commit();

    pdl_trigger();
    pdl_wait();       // d_h from gemm_{t-1} now visible

    // ---- gp = tanh(h @ W_g^T + b_g) (per warp) ----
    float4 hv = *reinterpret_cast<const float4*>(&d_h[b * 128 + lane * 4]);
    float gp[3];
#pragma unroll
    for (int k = 0; k < 3; k++) {
        float4 wv = __ldg(reinterpret_cast<const float4*>(&W_g[k * 128 + lane * 4]));
        float p = hv.x * wv.x + hv.y * wv.y + hv.z * wv.z + hv.w * wv.w;
#pragma unroll
        for (int o = 16; o > 0; o >>= 1) p += __shfl_xor_sync(0xffffffffu, p, o);
        gp[k] = tanhf(p + __ldg(&b_g[k]));
    }

    // ---- NORMALIZED Cauchy filterbanks, fp16 hi/lo, straight into smem ----
    {
        float ad  = fabsf(gp[2]);
        float dlt = 8.0f * (1.0f - ad);
        float gam = expf(1.0f - 2.0f * ad);
        float ig  = 1.0f / gam;
        float cpre = 1.0f / (3.14159265358979323f * gam);
        float fi0 = (float)(2 * lane), fi1 = fi0 + 1.0f;
#pragma unroll
        for (int a = 0; a < 2; a++) {
            float center = 31.5f * (gp[a] + 1.0f);
            uint32_t base = (a == 0) ? (uint32_t)GL2_FH(wid) : (uint32_t)GL2_FW(wid);
#pragma unroll
            for (int t = 0; t < 8; t++) {
                float gpix = center + dlt * ((float)t - 3.5f);
                float u0 = (fi0 - gpix) * ig, u1 = (fi1 - gpix) * ig;
                float v0 = __fdividef(cpre, 1.0f + u0 * u0);
                float v1 = __fdividef(cpre, 1.0f + u1 * u1);
                float s = v0 + v1;
#pragma unroll
                for (int o = 16; o > 0; o >>= 1) s += __shfl_xor_sync(0xffffffffu, s, o);
                float inv = __fdividef(1.0f, s + 1e-4f);
                v0 *= inv; v1 *= inv;
                uint32_t hi2 = pack_h2(v0, v1);
                __half2 hh = *reinterpret_cast<__half2*>(&hi2);
                float2 hf = __half22float2(hh);
                uint32_t lo2 = pack_h2(v0 - hf.x, v1 - hf.y);
                char* dst = gsm + base + t * 144 + lane * 4;
                *reinterpret_cast<uint32_t*>(dst) = hi2;          // hi: row t
                *reinterpret_cast<uint32_t*>(dst + 1152) = lo2;   // lo: row t+8
            }
        }
    }
    cp_wait<0>();
    __syncthreads();   // image tiles were cp.async'ed cooperatively across warps

    // ---- G1: single pass; A rows 0-7 = Fh_hi, rows 8-15 = Fh_lo ----
    float acc[8][4];
#pragma unroll
    for (int nt = 0; nt < 8; nt++)
#pragma unroll
        for (int q = 0; q < 4; q++) acc[nt][q] = 0.0f;

    uint32_t fh   = sb + GL2_FH(wid) + (lane & 15) * 144 + (lane >> 4) * 16;
    uint32_t imgb = sb + GL2_IMG(wid) + (lane & 15) * 144 + (lane >> 4) * 16;

#pragma unroll
    for (int kk = 0; kk < 4; kk++) {
        uint32_t ah[4];
        ldm_x4(ah, fh + kk * 32);
#pragma unroll
        for (int nt2 = 0; nt2 < 4; nt2++) {
            uint32_t bb[4];
            ldm_x4_t(bb, imgb + kk * (16 * 144) + nt2 * 32);
            mma_f16(acc[2 * nt2],     ah, bb);
            mma_f16(acc[2 * nt2 + 1], ah, bb + 2);
        }
    }

    // P_true[t] = hi-rows + lo-rows
    float ps[8][2];
#pragma unroll
    for (int nt = 0; nt < 8; nt++) {
        ps[nt][0] = acc[nt][0] + acc[nt][2];
        ps[nt][1] = acc[nt][1] + acc[nt][3];
    }

    // ---- G2: x[8,8] = P(hi+lo) @ FwB(hi+lo, minus lo*lo) ----
    float acc2[4] = {0.0f, 0.0f, 0.0f, 0.0f};
    uint32_t fwb = sb + GL2_FW(wid) + (lane & 7) * 144 + ((lane >> 3) & 1) * 16;
#pragma unroll
    for (int kk2 = 0; kk2 < 4; kk2++) {
        float p0 = ps[2 * kk2][0],     p1 = ps[2 * kk2][1];
        float q0 = ps[2 * kk2 + 1][0], q1 = ps[2 * kk2 + 1][1];
        uint32_t ah[4], al[4];
        ah[0] = pack_h2(p0, p1);
        ah[2] = pack_h2(q0, q1);
        ah[1] = 0u; ah[3] = 0u;
        {
            __half2 h0 = *reinterpret_cast<__half2*>(&ah[0]);
            __half2 h2 = *reinterpret_cast<__half2*>(&ah[2]);
            float2 f0 = __half22float2(h0);
            float2 f2 = __half22float2(h2);
            al[0] = pack_h2(p0 - f0.x, p1 - f0.y);
            al[2] = pack_h2(q0 - f2.x, q1 - f2.y);
            al[1] = 0u; al[3] = 0u;
        }
        uint32_t bh[2], bl[2];
        ldm_x2(bh, fwb + kk2 * 32);
        ldm_x2(bl, fwb + 1152 + kk2 * 32);
        mma_f16(acc2, ah, bh);
        mma_f16(acc2, al, bh);
        mma_f16(acc2, ah, bl);
    }

    // ---- writeback x (rows 0..7 valid) ----
    {
        int t = lane >> 2, c2 = (lane & 3) * 2;
        float v0 = acc2[0], v1 = acc2[1];
        __nv_bfloat16 h0 = __float2bfloat16(v0);
        __nv_bfloat16 h1 = __float2bfloat16(v1);
        __nv_bfloat162 hi2 = __nv_bfloat162(h0, h1);
        __nv_bfloat162 lo2 = __nv_bfloat162(
            __float2bfloat16(v0 - __bfloat162float(h0)),
            __float2bfloat16(v1 - __bfloat162float(h1)));
        *reinterpret_cast<__nv_bfloat162*>(&d_x_hi[b * 64 + t * 8 + c2]) = hi2;
        *reinterpret_cast<__nv_bfloat162*>(&d_x_lo[b * 64 + t * 8 + c2]) = lo2;
    }
}

// ---------------- fused GEMM (mma.sync bf16 split) + LSTM --------------------
// grid (128, 4), 256 threads = 8 warps (wm 0..1 x wn 0..3). CTA tile M=32 x N=128.
#define SA_OFF(b) ((b) * 4608)
#define SB_OFF(b) (9216 + (b) * 18432)
#define GS_TOTAL  46080

__global__ __launch_bounds__(256) void gemm_lstm_kernel(float* __restrict__ out, int last)
{
    extern __shared__ char smem[];
    uint32_t sb = smem_u32(smem);
    int tid = threadIdx.x;
    int wid = tid >> 5, lane = tid & 31;
    int wm = wid & 1, wn = wid >> 1;          // rows wm*16..+15, cols wn*32..+31
    int bm0 = blockIdx.x * 32;
    int bn0 = blockIdx.y * 128;
    int j0 = bn0 >> 2;

    const int tva[3] = {0, 0, 1};
    const int tvb[3] = {0, 1, 0};

    float acc[4][4];
#pragma unroll
    for (int nt = 0; nt < 4; nt++)
#pragma unroll
        for (int q = 0; q < 4; q++) acc[nt][q] = 0.0f;

    int ldr = tid >> 3;          // 0..31
    int ldc = tid & 7;           // 16B segment

    // ---- static prefetch: chunk0 B tile (W_hi, k block 0) before grid wait ----
#pragma unroll
    for (int p_ = 0; p_ < 4; p_++) {
        int r_ = ldr + p_ * 32;
        cp_async16(sb + SB_OFF(0) + r_ * 144 + ldc * 16,
                   d_W_hi + (bn0 + r_) * 192 + ldc * 8);
    }
    cp_commit();                 // group g0

    pdl_trigger();
    pdl_wait();                  // glimpse_t (and transitively gemm_{t-1}) complete

    // chunk0 A tile (x_hi) — dependent data
    cp_async16(sb + SA_OFF(0) + ldr * 144 + ldc * 16,
               d_x_hi + (bm0 + ldr) * 64 + ldc * 8);
    cp_commit();                 // group g1

#define ISSUE_LOADS(c, buf) do {                                                   \
        int t_ = (c) / 3, kb_ = (c) % 3;                                           \
        const __nv_bfloat16* xs_ = tva[t_] ? d_x_lo : d_x_hi;                      \
        const __nv_bfloat16* hs_ = tva[t_] ? d_h_lo : d_h_hi;                      \
        const __nv_bfloat16* ws_ = tvb[t_] ? d_W_lo : d_W_hi;                      \
        {                                                                          \
            const __nv_bfloat16* ga_;                                              \
            if (kb_ == 0) ga_ = xs_ + (bm0 + ldr) * 64 + ldc * 8;                  \
            else          ga_ = hs_ + (bm0 + ldr) * 128 + (kb_ - 1) * 64 + ldc * 8;\
            cp_async16(sb + SA_OFF(buf) + ldr * 144 + ldc * 16, ga_);              \
        }                                                                          \
        _Pragma("unroll")                                                          \
        for (int p_ = 0; p_ < 4; p_++) {                                           \
            int r_ = ldr + p_ * 32;                                                \
            const __nv_bfloat16* gb_ = ws_ + (bn0 + r_) * 192 + kb_ * 64 + ldc * 8;\
            cp_async16(sb + SB_OFF(buf) + r_ * 144 + ldc * 16, gb_);               \
        }                                                                          \
        cp_commit();                                                               \
    } while (0)

    uint32_t a_rowofs = (uint32_t)((lane & 15) * 144 + (lane >> 4) * 16);
    uint32_t b_rowofs = (uint32_t)((lane & 7) * 144 + ((lane >> 3) & 1) * 16);

    for (int c = 0; c < 9; c++) {
        int buf = c & 1;
        if (c < 8) ISSUE_LOADS(c + 1, buf ^ 1);
        if (c < 8) cp_wait<1>(); else cp_wait<0>();
        __syncthreads();

        uint32_t abase = sb + SA_OFF(buf) + wm * 16 * 144 + a_rowofs;
        uint32_t bbase = sb + SB_OFF(buf) + wn * 32 * 144 + b_rowofs;

#pragma unroll
        for (int ks = 0; ks < 4; ks++) {
            uint32_t a[4], bfr[4][2];
            ldm_x4(a, abase + ks * 32);
#pragma unroll
            for (int nt = 0; nt < 4; nt++)
                ldm_x2(bfr[nt], bbase + nt * (8 * 144) + ks * 32);
#pragma unroll
            for (int nt = 0; nt < 4; nt++)
                mma_bf16(acc[nt], a, bfr[nt]);
        }
        __syncthreads();
    }
#undef ISSUE_LOADS

    // store accumulators to gates smem tile (overlays sA/sB — dead now)
    float* g_s = reinterpret_cast<float*>(smem);   // [32][136]
    {
        int r0 = wm * 16 + (lane >> 2);
        int c0 = wn * 32 + (lane & 3) * 2;
#pragma unroll
        for (int nt = 0; nt < 4; nt++) {
            int col = c0 + nt * 8;
            *reinterpret_cast<float2*>(&g_s[r0 * 136 + col]) =
                make_float2(acc[nt][0], acc[nt][1]);
            *reinterpret_cast<float2*>(&g_s[(r0 + 8) * 136 + col]) =
                make_float2(acc[nt][2], acc[nt][3]);
        }
    }
    __syncthreads();

    // fused LSTM pointwise, coalesced global traffic
    const float4* bias4 = reinterpret_cast<const float4*>(d_bias + bn0);
#pragma unroll
    for (int i = tid; i < 32 * 32; i += 256) {
        int row = i >> 5, j = i & 31;
        float4 g4 = *reinterpret_cast<const float4*>(&g_s[row * 136 + 4 * j]);
        float4 b4 = __ldg(&bias4[j]);
        float gi = g4.x + b4.x;
        float gf = g4.y + b4.y;
        float gg = g4.z + b4.z;
        float go = g4.w + b4.w;
        int gidx = (bm0 + row) * 128 + j0 + j;
        float co = d_c[gidx];
        float si = 1.0f / (1.0f + expf(-gi));
        float sf = 1.0f / (1.0f + expf(-gf));
        float so = 1.0f / (1.0f + expf(-go));
        float cn = sf * co + si * tanhf(gg);
        float hn = so * tanhf(cn);
        d_c[gidx] = cn;
        if (last) {
            out[gidx] = hn;
        } else {
            d_h[gidx] = hn;
            __nv_bfloat16 hi = __float2bfloat16(hn);
            d_h_hi[gidx] = hi;
            d_h_lo[gidx] = __float2bfloat16(hn - __bfloat162float(hi));
        }
    }
}

// ---------------- launch ----------------------------------------------------
extern "C" void kernel_launch(void* const* d_in, const int* in_sizes, int n_in,
                              void* d_out, int out_size)
{
    const float* imgs = (const float*)d_in[0];
    const float* W_ih = (const float*)d_in[1];
    const float* W_hh = (const float*)d_in[2];
    const float* b_ih = (const float*)d_in[3];
    const float* b_hh = (const float*)d_in[4];
    const float* W_g  = (const float*)d_in[5];
    const float* b_g  = (const float*)d_in[6];
    float* out = (float*)d_out;

    static int smem_set = 0;
    if (!smem_set) {
        cudaFuncSetAttribute(gemm_lstm_kernel,
                             cudaFuncAttributeMaxDynamicSharedMemorySize, GS_TOTAL);
        cudaFuncSetAttribute(glimpse_kernel,
                             cudaFuncAttributeMaxDynamicSharedMemorySize, GL2_TOTAL);
        smem_set = 1;
    }

    prologue_kernel<<<10624, 256>>>(imgs, W_ih, W_hh, b_ih, b_hh);

    cudaLaunchAttribute pdl_attr[1];
    pdl_attr[0].id = cudaLaunchAttributeProgrammaticStreamSerialization;
    pdl_attr[0].val.programmaticStreamSerializationAllowed = 1;

    for (int t = 0; t < NSTEP; t++) {
        {
            cudaLaunchConfig_t cfg = {};
            cfg.gridDim = dim3(BATCH / 4, 1, 1);
            cfg.blockDim = dim3(128, 1, 1);
            cfg.dynamicSmemBytes = GL2_TOTAL;
            cfg.stream = 0;
            cfg.attrs = pdl_attr;
            cfg.numAttrs = 1;
            cudaLaunchKernelEx(&cfg, glimpse_kernel, t & 1, W_g, b_g);
        }
        {
            cudaLaunchConfig_t cfg = {};
            cfg.gridDim = dim3(128, 4, 1);
            cfg.blockDim = dim3(256, 1, 1);
            cfg.dynamicSmemBytes = GS_TOTAL;
            cfg.stream = 0;
            cfg.attrs = pdl_attr;
            cfg.numAttrs = 1;
            cudaLaunchKernelEx(&cfg, gemm_lstm_kernel, out,
                               (t == NSTEP - 1) ? 1 : 0);
        }
    }
}

// round 12
// speedup vs baseline: 1.0018x; 1.0018x over previous
#include <cuda_runtime.h>
#include <cuda_bf16.h>
#include <cuda_fp16.h>
#include <math.h>
#include <stdint.h>

#define BATCH 4096
#define HID 128
#define NSTEP 16

// ---------------- persistent state (device globals; no allocations) ----------
__device__ __align__(16) float d_h[BATCH * HID];
__device__ __align__(16) float d_c[BATCH * HID];
__device__ __align__(16) __nv_bfloat16 d_h_hi[BATCH * HID];
__device__ __align__(16) __nv_bfloat16 d_h_lo[BATCH * HID];
__device__ __align__(16) __nv_bfloat16 d_x_hi[BATCH * 64];
__device__ __align__(16) __nv_bfloat16 d_x_lo[BATCH * 64];
__device__ __align__(16) __nv_bfloat16 d_W_hi[512 * 192];   // reordered cols: n' = j*4+gate
__device__ __align__(16) __nv_bfloat16 d_W_lo[512 * 192];
__device__ __align__(16) float d_bias[512];                  // reordered
__device__ __align__(16) __half d_img_h[(size_t)BATCH * 2 * 4096];  // fp16 images (67MB)

// ---------------- helpers ----------------------------------------------------
__device__ __forceinline__ uint32_t smem_u32(const void* p) {
    uint32_t a;
    asm("{ .reg .u64 t; cvta.to.shared.u64 t, %1; cvt.u32.u64 %0, t; }" : "=r"(a) : "l"(p));
    return a;
}
__device__ __forceinline__ void cp_async16(uint32_t dst, const void* src) {
    asm volatile("cp.async.cg.shared.global [%0], [%1], 16;" :: "r"(dst), "l"(src) : "memory");
}
__device__ __forceinline__ uint64_t mk_evict_last_policy() {
    uint64_t p;
    asm("createpolicy.fractional.L2::evict_last.b64 %0, 1.0;" : "=l"(p));
    return p;
}
__device__ __forceinline__ void cp_async16_el(uint32_t dst, const void* src, uint64_t pol) {
    asm volatile("cp.async.cg.shared.global.L2::cache_hint [%0], [%1], 16, %2;"
                 :: "r"(dst), "l"(src), "l"(pol) : "memory");
}
__device__ __forceinline__ void st_global_el_v2(void* p, uint32_t a, uint32_t b, uint64_t pol) {
    asm volatile("st.global.L2::cache_hint.v2.u32 [%0], {%1, %2}, %3;"
                 :: "l"(p), "r"(a), "r"(b), "l"(pol) : "memory");
}
__device__ __forceinline__ void cp_commit() {
    asm volatile("cp.async.commit_group;" ::: "memory");
}
template <int N>
__device__ __forceinline__ void cp_wait() {
    asm volatile("cp.async.wait_group %0;" :: "n"(N) : "memory");
}
__device__ __forceinline__ void pdl_trigger() {
    asm volatile("griddepcontrol.launch_dependents;");
}
__device__ __forceinline__ void pdl_wait() {
    asm volatile("griddepcontrol.wait;" ::: "memory");
}
__device__ __forceinline__ void ldm_x4(uint32_t* r, uint32_t a) {
    asm volatile("ldmatrix.sync.aligned.m8n8.x4.shared.b16 {%0,%1,%2,%3}, [%4];"
                 : "=r"(r[0]), "=r"(r[1]), "=r"(r[2]), "=r"(r[3]) : "r"(a));
}
__device__ __forceinline__ void ldm_x4_t(uint32_t* r, uint32_t a) {
    asm volatile("ldmatrix.sync.aligned.m8n8.x4.trans.shared.b16 {%0,%1,%2,%3}, [%4];"
                 : "=r"(r[0]), "=r"(r[1]), "=r"(r[2]), "=r"(r[3]) : "r"(a));
}
__device__ __forceinline__ void ldm_x2(uint32_t* r, uint32_t a) {
    asm volatile("ldmatrix.sync.aligned.m8n8.x2.shared.b16 {%0,%1}, [%2];"
                 : "=r"(r[0]), "=r"(r[1]) : "r"(a));
}
__device__ __forceinline__ void mma_bf16(float* d, const uint32_t* a, const uint32_t* b) {
    asm volatile(
        "mma.sync.aligned.m16n8k16.row.col.f32.bf16.bf16.f32 "
        "{%0,%1,%2,%3}, {%4,%5,%6,%7}, {%8,%9}, {%0,%1,%2,%3};"
        : "+f"(d[0]), "+f"(d[1]), "+f"(d[2]), "+f"(d[3])
        : "r"(a[0]), "r"(a[1]), "r"(a[2]), "r"(a[3]), "r"(b[0]), "r"(b[1]));
}
__device__ __forceinline__ void mma_f16(float* d, const uint32_t* a, const uint32_t* b) {
    asm volatile(
        "mma.sync.aligned.m16n8k16.row.col.f32.f16.f16.f32 "
        "{%0,%1,%2,%3}, {%4,%5,%6,%7}, {%8,%9}, {%0,%1,%2,%3};"
        : "+f"(d[0]), "+f"(d[1]), "+f"(d[2]), "+f"(d[3])
        : "r"(a[0]), "r"(a[1]), "r"(a[2]), "r"(a[3]), "r"(b[0]), "r"(b[1]));
}
__device__ __forceinline__ uint32_t pack_h2(float x, float y) {
    __half2 h = __floats2half2_rn(x, y);
    return *reinterpret_cast<uint32_t*>(&h);
}

// ---------------- merged prologue --------------------------------------------
// blocks [0,8192): img fp32->fp16 (stored with evict_last policy so both
// images pin in L2); [8192,10240): zero state; [10240,10624): weights
__global__ void prologue_kernel(const float* __restrict__ imgs,
                                const float* __restrict__ W_ih,
                                const float* __restrict__ W_hh,
                                const float* __restrict__ b_ih,
                                const float* __restrict__ b_hh) {
    int bid = blockIdx.x, tid = threadIdx.x;
    if (bid < 8192) {
        uint64_t pol = mk_evict_last_policy();
        const float4* in4 = reinterpret_cast<const float4*>(imgs);
        uint2* out2 = reinterpret_cast<uint2*>(d_img_h);
        for (int i = bid * 256 + tid; i < 8388608; i += 8192 * 256) {
            float4 v = in4[i];
            __half2 a = __floats2half2_rn(v.x, v.y);
            __half2 c = __floats2half2_rn(v.z, v.w);
            uint32_t ax = *reinterpret_cast<uint32_t*>(&a);
            uint32_t cx = *reinterpret_cast<uint32_t*>(&c);
            st_global_el_v2(out2 + i, ax, cx, pol);
        }
    } else if (bid < 10240) {
        int i = (bid - 8192) * 256 + tid;    // exactly BATCH*HID
        d_h[i] = 0.0f; d_c[i] = 0.0f;
        d_h_hi[i] = __float2bfloat16(0.0f);
        d_h_lo[i] = __float2bfloat16(0.0f);
    } else {
        int idx = (bid - 10240) * 256 + tid; // exactly 512*192
        int np = idx / 192, k = idx % 192;
        int gate = np & 3, j = np >> 2;
        int orig = gate * 128 + j;
        float w = (k < 64) ? W_ih[orig * 64 + k] : W_hh[orig * 128 + (k - 64)];
        __nv_bfloat16 hi = __float2bfloat16(w);
        __nv_bfloat16 lo = __float2bfloat16(w - __bfloat162float(hi));
        d_W_hi[np * 192 + k] = hi;
        d_W_lo[np * 192 + k] = lo;
        if (k == 0) d_bias[np] = b_ih[orig] + b_hh[orig];
    }
}

// ---------------- glimpse (tensor-core, packed hi/lo, EXPLICIT norm) ---------
// 128 threads = 4 warps, one sample per warp.
// smem: img[s] @ s*9216 (64 rows x 144B fp16)
//       FhA[s] @ 36864 + s*2304 (16 rows x 144B: rows 0-7 = hi, 8-15 = lo)
//       FwB[s] @ 46080 + s*2304 (hi 8 rows @0, lo 8 rows @1152)
#define GL2_IMG(s)    ((s) * 9216)
#define GL2_FH(s)     (36864 + (s) * 2304)
#define GL2_FW(s)     (46080 + (s) * 2304)
#define GL2_TOTAL     55296

__global__ __launch_bounds__(128) void glimpse_kernel(
    int sel, const float* __restrict__ W_g, const float* __restrict__ b_g)
{
    extern __shared__ char gsm[];
    uint32_t sb = smem_u32(gsm);
    int tid = threadIdx.x, wid = tid >> 5, lane = tid & 31;
    int b0 = blockIdx.x * 4;
    int b = b0 + wid;

    // ---- static prefetch (images, L2 evict_last) BEFORE grid-dependency wait
    uint64_t pol = mk_evict_last_policy();
#pragma unroll
    for (int j = 0; j < 16; j++) {
        int idx = tid + j * 128;
        int s = idx >> 9, r = (idx >> 3) & 63, c = idx & 7;
        const __half* src = d_img_h + ((size_t)(b0 + s) * 2 + (size_t)sel) * 4096 + r * 64 + c * 8;
        cp_async16_el(sb + GL2_IMG(s) + r * 144 + c * 16, src, pol);
    }
    cp_commit();

    pdl_trigger();
    pdl_wait();       // d_h from gemm_{t-1} now visible

    // ---- gp = tanh(h @ W_g^T + b_g) (per warp) ----
    float4 hv = *reinterpret_cast<const float4*>(&d_h[b * 128 + lane * 4]);
    float gp[3];
#pragma unroll
    for (int k = 0; k < 3; k++) {
        float4 wv = __ldg(reinterpret_cast<const float4*>(&W_g[k * 128 + lane * 4]));
        float p = hv.x * wv.x + hv.y * wv.y + hv.z * wv.z + hv.w * wv.w;
#pragma unroll
        for (int o = 16; o > 0; o >>= 1) p += __shfl_xor_sync(0xffffffffu, p, o);
        gp[k] = tanhf(p + __ldg(&b_g[k]));
    }

    // ---- NORMALIZED Cauchy filterbanks, fp16 hi/lo, straight into smem ----
    {
        float ad  = fabsf(gp[2]);
        float dlt = 8.0f * (1.0f - ad);
        float gam = expf(1.0f - 2.0f * ad);
        float ig  = 1.0f / gam;
        float cpre = 1.0f / (3.14159265358979323f * gam);
        float fi0 = (float)(2 * lane), fi1 = fi0 + 1.0f;
#pragma unroll
        for (int a = 0; a < 2; a++) {
            float center = 31.5f * (gp[a] + 1.0f);
            uint32_t base = (a == 0) ? (uint32_t)GL2_FH(wid) : (uint32_t)GL2_FW(wid);
#pragma unroll
            for (int t = 0; t < 8; t++) {
                float gpix = center + dlt * ((float)t - 3.5f);
                float u0 = (fi0 - gpix) * ig, u1 = (fi1 - gpix) * ig;
                float v0 = __fdividef(cpre, 1.0f + u0 * u0);
                float v1 = __fdividef(cpre, 1.0f + u1 * u1);
                float s = v0 + v1;
#pragma unroll
                for (int o = 16; o > 0; o >>= 1) s += __shfl_xor_sync(0xffffffffu, s, o);
                float inv = __fdividef(1.0f, s + 1e-4f);
                v0 *= inv; v1 *= inv;
                uint32_t hi2 = pack_h2(v0, v1);
                __half2 hh = *reinterpret_cast<__half2*>(&hi2);
                float2 hf = __half22float2(hh);
                uint32_t lo2 = pack_h2(v0 - hf.x, v1 - hf.y);
                char* dst = gsm + base + t * 144 + lane * 4;
                *reinterpret_cast<uint32_t*>(dst) = hi2;          // hi: row t
                *reinterpret_cast<uint32_t*>(dst + 1152) = lo2;   // lo: row t+8
            }
        }
    }
    cp_wait<0>();
    __syncthreads();   // image tiles were cp.async'ed cooperatively across warps

    // ---- G1: single pass; A rows 0-7 = Fh_hi, rows 8-15 = Fh_lo ----
    float acc[8][4];
#pragma unroll
    for (int nt = 0; nt < 8; nt++)
#pragma unroll
        for (int q = 0; q < 4; q++) acc[nt][q] = 0.0f;

    uint32_t fh   = sb + GL2_FH(wid) + (lane & 15) * 144 + (lane >> 4) * 16;
    uint32_t imgb = sb + GL2_IMG(wid) + (lane & 15) * 144 + (lane >> 4) * 16;

#pragma unroll
    for (int kk = 0; kk < 4; kk++) {
        uint32_t ah[4];
        ldm_x4(ah, fh + kk * 32);
#pragma unroll
        for (int nt2 = 0; nt2 < 4; nt2++) {
            uint32_t bb[4];
            ldm_x4_t(bb, imgb + kk * (16 * 144) + nt2 * 32);
            mma_f16(acc[2 * nt2],     ah, bb);
            mma_f16(acc[2 * nt2 + 1], ah, bb + 2);
        }
    }

    // P_true[t] = hi-rows + lo-rows
    float ps[8][2];
#pragma unroll
    for (int nt = 0; nt < 8; nt++) {
        ps[nt][0] = acc[nt][0] + acc[nt][2];
        ps[nt][1] = acc[nt][1] + acc[nt][3];
    }

    // ---- G2: x[8,8] = P(hi+lo) @ FwB(hi+lo, minus lo*lo) ----
    float acc2[4] = {0.0f, 0.0f, 0.0f, 0.0f};
    uint32_t fwb = sb + GL2_FW(wid) + (lane & 7) * 144 + ((lane >> 3) & 1) * 16;
#pragma unroll
    for (int kk2 = 0; kk2 < 4; kk2++) {
        float p0 = ps[2 * kk2][0],     p1 = ps[2 * kk2][1];
        float q0 = ps[2 * kk2 + 1][0], q1 = ps[2 * kk2 + 1][1];
        uint32_t ah[4], al[4];
        ah[0] = pack_h2(p0, p1);
        ah[2] = pack_h2(q0, q1);
        ah[1] = 0u; ah[3] = 0u;
        {
            __half2 h0 = *reinterpret_cast<__half2*>(&ah[0]);
            __half2 h2 = *reinterpret_cast<__half2*>(&ah[2]);
            float2 f0 = __half22float2(h0);
            float2 f2 = __half22float2(h2);
            al[0] = pack_h2(p0 - f0.x, p1 - f0.y);
            al[2] = pack_h2(q0 - f2.x, q1 - f2.y);
            al[1] = 0u; al[3] = 0u;
        }
        uint32_t bh[2], bl[2];
        ldm_x2(bh, fwb + kk2 * 32);
        ldm_x2(bl, fwb + 1152 + kk2 * 32);
        mma_f16(acc2, ah, bh);
        mma_f16(acc2, al, bh);
        mma_f16(acc2, ah, bl);
    }

    // ---- writeback x (rows 0..7 valid) ----
    {
        int t = lane >> 2, c2 = (lane & 3) * 2;
        float v0 = acc2[0], v1 = acc2[1];
        __nv_bfloat16 h0 = __float2bfloat16(v0);
        __nv_bfloat16 h1 = __float2bfloat16(v1);
        __nv_bfloat162 hi2 = __nv_bfloat162(h0, h1);
        __nv_bfloat162 lo2 = __nv_bfloat162(
            __float2bfloat16(v0 - __bfloat162float(h0)),
            __float2bfloat16(v1 - __bfloat162float(h1)));
        *reinterpret_cast<__nv_bfloat162*>(&d_x_hi[b * 64 + t * 8 + c2]) = hi2;
        *reinterpret_cast<__nv_bfloat162*>(&d_x_lo[b * 64 + t * 8 + c2]) = lo2;
    }
}

// ---------------- fused GEMM (mma.sync bf16 split) + LSTM --------------------
// grid (128, 4), 256 threads = 8 warps (wm 0..1 x wn 0..3). CTA tile M=32 x N=128.
#define SA_OFF(b) ((b) * 4608)
#define SB_OFF(b) (9216 + (b) * 18432)
#define GS_TOTAL  46080

__global__ __launch_bounds__(256) void gemm_lstm_kernel(float* __restrict__ out, int last)
{
    extern __shared__ char smem[];
    uint32_t sb = smem_u32(smem);
    int tid = threadIdx.x;
    int wid = tid >> 5, lane = tid & 31;
    int wm = wid & 1, wn = wid >> 1;          // rows wm*16..+15, cols wn*32..+31
    int bm0 = blockIdx.x * 32;
    int bn0 = blockIdx.y * 128;
    int j0 = bn0 >> 2;

    const int tva[3] = {0, 0, 1};
    const int tvb[3] = {0, 1, 0};

    float acc[4][4];
#pragma unroll
    for (int nt = 0; nt < 4; nt++)
#pragma unroll
        for (int q = 0; q < 4; q++) acc[nt][q] = 0.0f;

    int ldr = tid >> 3;          // 0..31
    int ldc = tid & 7;           // 16B segment

    // ---- static prefetch: chunk0 B tile (W_hi, k block 0) before grid wait ----
#pragma unroll
    for (int p_ = 0; p_ < 4; p_++) {
        int r_ = ldr + p_ * 32;
        cp_async16(sb + SB_OFF(0) + r_ * 144 + ldc * 16,
                   d_W_hi + (bn0 + r_) * 192 + ldc * 8);
    }
    cp_commit();                 // group g0

    pdl_trigger();
    pdl_wait();                  // glimpse_t (and transitively gemm_{t-1}) complete

    // chunk0 A tile (x_hi) — dependent data
    cp_async16(sb + SA_OFF(0) + ldr * 144 + ldc * 16,
               d_x_hi + (bm0 + ldr) * 64 + ldc * 8);
    cp_commit();                 // group g1

#define ISSUE_LOADS(c, buf) do {                                                   \
        int t_ = (c) / 3, kb_ = (c) % 3;                                           \
        const __nv_bfloat16* xs_ = tva[t_] ? d_x_lo : d_x_hi;                      \
        const __nv_bfloat16* hs_ = tva[t_] ? d_h_lo : d_h_hi;                      \
        const __nv_bfloat16* ws_ = tvb[t_] ? d_W_lo : d_W_hi;                      \
        {                                                                          \
            const __nv_bfloat16* ga_;                                              \
            if (kb_ == 0) ga_ = xs_ + (bm0 + ldr) * 64 + ldc * 8;                  \
            else          ga_ = hs_ + (bm0 + ldr) * 128 + (kb_ - 1) * 64 + ldc * 8;\
            cp_async16(sb + SA_OFF(buf) + ldr * 144 + ldc * 16, ga_);              \
        }                                                                          \
        _Pragma("unroll")                                                          \
        for (int p_ = 0; p_ < 4; p_++) {                                           \
            int r_ = ldr + p_ * 32;                                                \
            const __nv_bfloat16* gb_ = ws_ + (bn0 + r_) * 192 + kb_ * 64 + ldc * 8;\
            cp_async16(sb + SB_OFF(buf) + r_ * 144 + ldc * 16, gb_);               \
        }                                                                          \
        cp_commit();                                                               \
    } while (0)

    uint32_t a_rowofs = (uint32_t)((lane & 15) * 144 + (lane >> 4) * 16);
    uint32_t b_rowofs = (uint32_t)((lane & 7) * 144 + ((lane >> 3) & 1) * 16);

    for (int c = 0; c < 9; c++) {
        int buf = c & 1;
        if (c < 8) ISSUE_LOADS(c + 1, buf ^ 1);
        if (c < 8) cp_wait<1>(); else cp_wait<0>();
        __syncthreads();

        uint32_t abase = sb + SA_OFF(buf) + wm * 16 * 144 + a_rowofs;
        uint32_t bbase = sb + SB_OFF(buf) + wn * 32 * 144 + b_rowofs;

#pragma unroll
        for (int ks = 0; ks < 4; ks++) {
            uint32_t a[4], bfr[4][2];
            ldm_x4(a, abase + ks * 32);
#pragma unroll
            for (int nt = 0; nt < 4; nt++)
                ldm_x2(bfr[nt], bbase + nt * (8 * 144) + ks * 32);
#pragma unroll
            for (int nt = 0; nt < 4; nt++)
                mma_bf16(acc[nt], a, bfr[nt]);
        }
        __syncthreads();
    }
#undef ISSUE_LOADS

    // store accumulators to gates smem tile (overlays sA/sB — dead now)
    float* g_s = reinterpret_cast<float*>(smem);   // [32][136]
    {
        int r0 = wm * 16 + (lane >> 2);
        int c0 = wn * 32 + (lane & 3) * 2;
#pragma unroll
        for (int nt = 0; nt < 4; nt++) {
            int col = c0 + nt * 8;
            *reinterpret_cast<float2*>(&g_s[r0 * 136 + col]) =
                make_float2(acc[nt][0], acc[nt][1]);
            *reinterpret_cast<float2*>(&g_s[(r0 + 8) * 136 + col]) =
                make_float2(acc[nt][2], acc[nt][3]);
        }
    }
    __syncthreads();

    // fused LSTM pointwise, coalesced global traffic
    const float4* bias4 = reinterpret_cast<const float4*>(d_bias + bn0);
#pragma unroll
    for (int i = tid; i < 32 * 32; i += 256) {
        int row = i >> 5, j = i & 31;
        float4 g4 = *reinterpret_cast<const float4*>(&g_s[row * 136 + 4 * j]);
        float4 b4 = __ldg(&bias4[j]);
        float gi = g4.x + b4.x;
        float gf = g4.y + b4.y;
        float gg = g4.z + b4.z;
        float go = g4.w + b4.w;
        int gidx = (bm0 + row) * 128 + j0 + j;
        float co = d_c[gidx];
        float si = 1.0f / (1.0f + expf(-gi));
        float sf = 1.0f / (1.0f + expf(-gf));
        float so = 1.0f / (1.0f + expf(-go));
        float cn = sf * co + si * tanhf(gg);
        float hn = so * tanhf(cn);
        d_c[gidx] = cn;
        if (last) {
            out[gidx] = hn;
        } else {
            d_h[gidx] = hn;
            __nv_bfloat16 hi = __float2bfloat16(hn);
            d_h_hi[gidx] = hi;
            d_h_lo[gidx] = __float2bfloat16(hn - __bfloat162float(hi));
        }
    }
}

// ---------------- launch ----------------------------------------------------
extern "C" void kernel_launch(void* const* d_in, const int* in_sizes, int n_in,
                              void* d_out, int out_size)
{
    const float* imgs = (const float*)d_in[0];
    const float* W_ih = (const float*)d_in[1];
    const float* W_hh = (const float*)d_in[2];
    const float* b_ih = (const float*)d_in[3];
    const float* b_hh = (const float*)d_in[4];
    const float* W_g  = (const float*)d_in[5];
    const float* b_g  = (const float*)d_in[6];
    float* out = (float*)d_out;

    static int smem_set = 0;
    if (!smem_set) {
        cudaFuncSetAttribute(gemm_lstm_kernel,
                             cudaFuncAttributeMaxDynamicSharedMemorySize, GS_TOTAL);
        cudaFuncSetAttribute(glimpse_kernel,
                             cudaFuncAttributeMaxDynamicSharedMemorySize, GL2_TOTAL);
        smem_set = 1;
    }

    prologue_kernel<<<10624, 256>>>(imgs, W_ih, W_hh, b_ih, b_hh);

    cudaLaunchAttribute pdl_attr[1];
    pdl_attr[0].id = cudaLaunchAttributeProgrammaticStreamSerialization;
    pdl_attr[0].val.programmaticStreamSerializationAllowed = 1;

    for (int t = 0; t < NSTEP; t++) {
        {
            cudaLaunchConfig_t cfg = {};
            cfg.gridDim = dim3(BATCH / 4, 1, 1);
            cfg.blockDim = dim3(128, 1, 1);
            cfg.dynamicSmemBytes = GL2_TOTAL;
            cfg.stream = 0;
            cfg.attrs = pdl_attr;
            cfg.numAttrs = 1;
            cudaLaunchKernelEx(&cfg, glimpse_kernel, t & 1, W_g, b_g);
        }
        {
            cudaLaunchConfig_t cfg = {};
            cfg.gridDim = dim3(128, 4, 1);
            cfg.blockDim = dim3(256, 1, 1);
            cfg.dynamicSmemBytes = GS_TOTAL;
            cfg.stream = 0;
            cfg.attrs = pdl_attr;
            cfg.numAttrs = 1;
            cudaLaunchKernelEx(&cfg, gemm_lstm_kernel, out,
                               (t == NSTEP - 1) ? 1 : 0);
        }
    }
}